// round 16
// baseline (speedup 1.0000x reference)
#include <cuda_runtime.h>
#include <cuda_fp16.h>
#include <cuda_fp8.h>
#include <cuda_bf16.h>
#include <math.h>

#define TT 16
#define NN 10000
#define EE 320000
#define EN (EE + NN)
#define FF 128
#define HH 256
#define LL 64
#define HL 256
#define LSTM_BLOCKS 8

// ---------------- device scratch ----------------
__device__ int   d_rowptr[NN + 1];
__device__ int   d_cnt[NN];
__device__ int   d_bsum[10];
__device__ __align__(16) int2 d_edge_enc[EN];   // {col, float_bits(nrm_enc)}
__device__ __align__(16) int2 d_edge_dec[EN];   // {col, float_bits(nrm_dec)}
__device__ float d_deg_enc[NN];
__device__ float d_deg_dec[NN];
__device__ float d_dis_enc[NN];
__device__ float d_dis_dec[NN];
__device__ __align__(16) float d_buf0[(size_t)TT * NN * HH];
__device__ __align__(16) float d_buf1[(size_t)TT * NN * HH];
__device__ __align__(16) __half d_hbuf[(size_t)TT * NN * HH];
__device__ __align__(16) unsigned char d_x8[(size_t)TT * NN * FF];   // xs in e4m3
__device__ __align__(16) unsigned char d_h8[(size_t)TT * NN * HH];   // fused GEMM out in e4m3
__device__ __align__(16) __half d_We0h[FF * HH];
__device__ __align__(16) __half d_We1h[HH * HH];
__device__ __align__(16) __half d_Wd0h[LL * HH];
__device__ __align__(16) __half d_Wd1h[HH * HH];
__device__ __align__(16) __half d_Wd2h[HH * FF];
__device__ __align__(16) __half d_Wih0h[LL * 4 * HL];
__device__ __align__(16) __half d_Whh0h[HL * 4 * HL];
__device__ __align__(16) __half d_Wih1h[HL * 4 * HL];
__device__ __align__(16) __half d_Whh1h[HL * 4 * HL];
__device__ float d_gpool[TT * HH];
__device__ float d_zs[TT * LL];
__device__ __align__(16) float d_gates[2][4 * HL];
__device__ float d_zfin[LL];
__device__ float d_sink;
__device__ int   d_idx64;

__device__ __forceinline__ void get_edge(const void* ei, int e, int& s, int& d) {
    if (d_idx64) {
        const long long* p = (const long long*)ei;
        s = (int)p[e];
        d = (int)p[EE + e];
    } else {
        const int* p = (const int*)ei;
        s = p[e];
        d = p[EE + e];
    }
}

// ---------------- preprocessing ----------------
__global__ void zero_kernel(const void* ei) {
    int i = blockIdx.x * blockDim.x + threadIdx.x;
    if (i < NN) { d_deg_enc[i] = 0.f; d_deg_dec[i] = 0.f; d_cnt[i] = 0; }
    if (i < TT * HH) d_gpool[i] = 0.f;
    if (blockIdx.x == 0 && threadIdx.x == 0) {
        const unsigned int* w = (const unsigned int*)ei;
        int is64 = 1;
        for (int k = 0; k < 64; ++k)
            if (w[2 * k + 1] != 0u) { is64 = 0; break; }
        d_idx64 = is64;
    }
}

__global__ void count_kernel(const void* ei, const float* __restrict__ ea) {
    int e = blockIdx.x * blockDim.x + threadIdx.x;
    if (e >= EN) return;
    int s, d; float w;
    if (e < EE) { get_edge(ei, e, s, d); w = ea[e]; }
    else { s = d = e - EE; w = 1.f; }
    atomicAdd(&d_deg_enc[d], w);
    atomicAdd(&d_deg_dec[d], 1.f);
}

__global__ __launch_bounds__(1024) void scanA_kernel() {
    __shared__ int sh[1024];
    int blk = blockIdx.x, tid = threadIdx.x;
    int idx = blk * 1000 + tid;
    int c = (tid < 1000) ? (int)d_deg_dec[idx] : 0;
    sh[tid] = c;
    __syncthreads();
    for (int off = 1; off < 1024; off <<= 1) {
        int v = (tid >= off) ? sh[tid - off] : 0;
        __syncthreads();
        sh[tid] += v;
        __syncthreads();
    }
    if (tid < 1000) {
        d_rowptr[idx] = sh[tid] - c;
        d_dis_enc[idx] = rsqrtf(d_deg_enc[idx]);
        d_dis_dec[idx] = rsqrtf(d_deg_dec[idx]);
    }
    if (tid == 1023) d_bsum[blk] = sh[1023];
}

__global__ __launch_bounds__(1024) void scanC_kernel() {
    __shared__ int off_sh;
    int blk = blockIdx.x, tid = threadIdx.x;
    if (tid == 0) {
        int o = 0;
        for (int i = 0; i < blk; ++i) o += d_bsum[i];
        off_sh = o;
        if (blk == 9) d_rowptr[NN] = o + d_bsum[9];
    }
    __syncthreads();
    int idx = blk * 1000 + tid;
    if (tid < 1000) d_rowptr[idx] += off_sh;
}

__global__ void fill_kernel(const void* ei, const float* __restrict__ ea) {
    int e = blockIdx.x * blockDim.x + threadIdx.x;
    if (e >= EN) return;
    int s, d; float w;
    if (e < EE) { get_edge(ei, e, s, d); w = ea[e]; }
    else { s = d = e - EE; w = 1.f; }
    int pos = d_rowptr[d] + atomicAdd(&d_cnt[d], 1);
    float ne = d_dis_enc[s] * w * d_dis_enc[d];
    float nd = d_dis_dec[s] * d_dis_dec[d];
    d_edge_enc[pos] = make_int2(s, __float_as_int(ne));
    d_edge_dec[pos] = make_int2(s, __float_as_int(nd));
}

// ---------------- L2 prefetch (warms Wfcd during LSTM) ----------------
__global__ void prefetch_kernel(const float4* __restrict__ p, int n4) {
    float acc = 0.f;
    for (int i = blockIdx.x * blockDim.x + threadIdx.x; i < n4; i += gridDim.x * blockDim.x) {
        float4 v = __ldg(p + i);
        acc += v.x + v.y + v.z + v.w;
    }
    if (acc == 1.234567e30f) d_sink = acc;
}

// ---------------- fused conversions: xs -> fp8, all weights -> fp16 ----------------
#define N2_XS    (TT * NN * FF / 2)
#define N2_WE0   (FF * HH / 2)
#define N2_WE1   (HH * HH / 2)
#define N2_WD0   (LL * HH / 2)
#define N2_WD1   (HH * HH / 2)
#define N2_WD2   (HH * FF / 2)
#define N2_WIH0  (LL * 4 * HL / 2)
#define N2_WHH0  (HL * 4 * HL / 2)
#define N2_WIH1  (HL * 4 * HL / 2)
#define N2_WHH1  (HL * 4 * HL / 2)
#define N2_TOT   (N2_XS + N2_WE0 + N2_WE1 + N2_WD0 + N2_WD1 + N2_WD2 + \
                  N2_WIH0 + N2_WHH0 + N2_WIH1 + N2_WHH1)

__global__ void f2h_all_kernel(const float* xs, const float* We0, const float* We1,
                               const float* Wd0, const float* Wd1, const float* Wd2,
                               const float* Wih0, const float* Whh0,
                               const float* Wih1, const float* Whh1,
                               unsigned short* hx8, __half2* hwe0, __half2* hwe1,
                               __half2* hwd0, __half2* hwd1, __half2* hwd2,
                               __half2* hwih0, __half2* hwhh0,
                               __half2* hwih1, __half2* hwhh1) {
    int i = blockIdx.x * blockDim.x + threadIdx.x;
    int off = i;
    if (off < N2_XS) {
        float2 v = ((const float2*)xs)[off];
        hx8[off] = __nv_cvt_float2_to_fp8x2(v, __NV_SATFINITE, __NV_E4M3);
        return;
    }
    const float* src; __half2* dst;
    off -= N2_XS;
    if (off < N2_WE0) { src = We0; dst = hwe0; }
    else if ((off -= N2_WE0) < N2_WE1) { src = We1; dst = hwe1; }
    else if ((off -= N2_WE1) < N2_WD0) { src = Wd0; dst = hwd0; }
    else if ((off -= N2_WD0) < N2_WD1) { src = Wd1; dst = hwd1; }
    else if ((off -= N2_WD1) < N2_WD2) { src = Wd2; dst = hwd2; }
    else if ((off -= N2_WD2) < N2_WIH0) { src = Wih0; dst = hwih0; }
    else if ((off -= N2_WIH0) < N2_WHH0) { src = Whh0; dst = hwhh0; }
    else if ((off -= N2_WHH0) < N2_WIH1) { src = Wih1; dst = hwih1; }
    else if ((off -= N2_WIH1) < N2_WHH1) { src = Whh1; dst = hwhh1; }
    else return;
    float2 v = ((const float2*)src)[off];
    dst[off] = __floats2half2_rn(v.x, v.y);
}

// ---------------- fp8x2 -> half2 ----------------
__device__ __forceinline__ __half2 fp8x2_h2(unsigned short s) {
    __half2_raw hr = __nv_cvt_fp8x2_to_halfraw2((__nv_fp8x2_storage_t)s, __NV_E4M3);
    return *(__half2*)&hr;
}

// ---------------- encoder layer0 agg: fp8 gathers, packed edges, HFMA2 ----------------
__global__ __launch_bounds__(128) void agg_enc0_kernel(const uint4* __restrict__ src,
                                                       uint4* __restrict__ dst) {
    int n = blockIdx.x;
    int tid = threadIdx.x;
    int f4 = tid & 7;
    int ts = tid >> 3;
    int beg = d_rowptr[n], end = d_rowptr[n + 1];
    size_t pb = (size_t)ts * NN * 8;
    __half2 acc[8];
#pragma unroll
    for (int i = 0; i < 8; ++i) acc[i] = __floats2half2_rn(0.f, 0.f);
    int e = beg;
    for (; e + 2 <= end; e += 2) {
        int2 r0 = __ldg(&d_edge_enc[e]);
        int2 r1 = __ldg(&d_edge_enc[e + 1]);
        float w0 = __int_as_float(r0.y);
        float w1 = __int_as_float(r1.y);
        __half2 w02 = __floats2half2_rn(w0, w0);
        __half2 w12 = __floats2half2_rn(w1, w1);
        uint4 v0 = __ldg(src + pb + (size_t)r0.x * 8 + f4);
        uint4 v1 = __ldg(src + pb + (size_t)r1.x * 8 + f4);
        const unsigned short* p0 = (const unsigned short*)&v0;
        const unsigned short* p1 = (const unsigned short*)&v1;
#pragma unroll
        for (int p = 0; p < 8; ++p) {
            acc[p] = __hfma2(fp8x2_h2(p0[p]), w02, acc[p]);
            acc[p] = __hfma2(fp8x2_h2(p1[p]), w12, acc[p]);
        }
    }
    if (e < end) {
        int2 r = __ldg(&d_edge_enc[e]);
        float w = __int_as_float(r.y);
        __half2 w2 = __floats2half2_rn(w, w);
        uint4 v = __ldg(src + pb + (size_t)r.x * 8 + f4);
        const unsigned short* p = (const unsigned short*)&v;
#pragma unroll
        for (int q = 0; q < 8; ++q)
            acc[q] = __hfma2(fp8x2_h2(p[q]), w2, acc[q]);
    }
    uint4 o[2];
    __half2* oh = (__half2*)o;
#pragma unroll
    for (int p = 0; p < 8; ++p) oh[p] = acc[p];
    uint4* dp = dst + ((size_t)ts * NN + n) * 16 + f4 * 2;
    dp[0] = o[0];
    dp[1] = o[1];
}

// ---------------- agg + bias + relu + mean-pool: fp8 gathers, packed edges, 8 nodes/block ----------------
__global__ __launch_bounds__(256) void agg_pool_kernel(const uint4* __restrict__ src,
                                                       const float* __restrict__ bias) {
    int tid = threadIdx.x;
    int f4 = tid & 15;
    int ts = tid >> 4;
    int n0 = blockIdx.x * 8;
    float b[16];
#pragma unroll
    for (int i = 0; i < 16; ++i) b[i] = bias[f4 * 16 + i];
    float pool[16];
#pragma unroll
    for (int i = 0; i < 16; ++i) pool[i] = 0.f;
    size_t pb = (size_t)ts * NN * 16;
    for (int n = n0; n < n0 + 8; ++n) {
        int beg = d_rowptr[n], end = d_rowptr[n + 1];
        __half2 acc[8];
#pragma unroll
        for (int i = 0; i < 8; ++i) acc[i] = __floats2half2_rn(0.f, 0.f);
        int e = beg;
        for (; e + 2 <= end; e += 2) {
            int2 r0 = __ldg(&d_edge_enc[e]);
            int2 r1 = __ldg(&d_edge_enc[e + 1]);
            float w0 = __int_as_float(r0.y);
            float w1 = __int_as_float(r1.y);
            __half2 w02 = __floats2half2_rn(w0, w0);
            __half2 w12 = __floats2half2_rn(w1, w1);
            uint4 v0 = __ldg(src + pb + (size_t)r0.x * 16 + f4);
            uint4 v1 = __ldg(src + pb + (size_t)r1.x * 16 + f4);
            const unsigned short* p0 = (const unsigned short*)&v0;
            const unsigned short* p1 = (const unsigned short*)&v1;
#pragma unroll
            for (int p = 0; p < 8; ++p) {
                acc[p] = __hfma2(fp8x2_h2(p0[p]), w02, acc[p]);
                acc[p] = __hfma2(fp8x2_h2(p1[p]), w12, acc[p]);
            }
        }
        if (e < end) {
            int2 r = __ldg(&d_edge_enc[e]);
            float w = __int_as_float(r.y);
            __half2 w2 = __floats2half2_rn(w, w);
            uint4 v = __ldg(src + pb + (size_t)r.x * 16 + f4);
            const unsigned short* p = (const unsigned short*)&v;
#pragma unroll
            for (int q = 0; q < 8; ++q)
                acc[q] = __hfma2(fp8x2_h2(p[q]), w2, acc[q]);
        }
#pragma unroll
        for (int i = 0; i < 8; ++i) {
            float2 f = __half22float2(acc[i]);
            pool[2 * i]     += fmaxf(f.x + b[2 * i], 0.f);
            pool[2 * i + 1] += fmaxf(f.y + b[2 * i + 1], 0.f);
        }
    }
#pragma unroll
    for (int i = 0; i < 16; ++i)
        atomicAdd(&d_gpool[ts * HH + f4 * 16 + i], pool[i] * (1.0f / NN));
}

// ---------------- decoder CSR aggregation (fp16 src, fp32 accum): packed edges ----------------
template<int C2, int NPB, bool RELU, bool OUTF>
__global__ void agg_dec_kernel(const __half2* __restrict__ src, void* __restrict__ dstv,
                               const float* __restrict__ bias) {
    int tid = threadIdx.x;
    int n = blockIdx.x * NPB + tid / C2;
    int f2 = tid % C2;
    if (n >= NN) return;
    int beg = d_rowptr[n], end = d_rowptr[n + 1];
    float ax0 = 0.f, ay0 = 0.f, ax1 = 0.f, ay1 = 0.f;
    float ax2 = 0.f, ay2 = 0.f, ax3 = 0.f, ay3 = 0.f;
    int e = beg;
    for (; e + 4 <= end; e += 4) {
        int2 r0 = __ldg(&d_edge_dec[e]);
        int2 r1 = __ldg(&d_edge_dec[e + 1]);
        int2 r2 = __ldg(&d_edge_dec[e + 2]);
        int2 r3 = __ldg(&d_edge_dec[e + 3]);
        float w0 = __int_as_float(r0.y);
        float w1 = __int_as_float(r1.y);
        float w2 = __int_as_float(r2.y);
        float w3 = __int_as_float(r3.y);
        float2 v0 = __half22float2(__ldg(&src[(size_t)r0.x * C2 + f2]));
        float2 v1 = __half22float2(__ldg(&src[(size_t)r1.x * C2 + f2]));
        float2 v2 = __half22float2(__ldg(&src[(size_t)r2.x * C2 + f2]));
        float2 v3 = __half22float2(__ldg(&src[(size_t)r3.x * C2 + f2]));
        ax0 += w0 * v0.x; ay0 += w0 * v0.y;
        ax1 += w1 * v1.x; ay1 += w1 * v1.y;
        ax2 += w2 * v2.x; ay2 += w2 * v2.y;
        ax3 += w3 * v3.x; ay3 += w3 * v3.y;
    }
    for (; e < end; ++e) {
        int2 r = __ldg(&d_edge_dec[e]);
        float w = __int_as_float(r.y);
        float2 v = __half22float2(__ldg(&src[(size_t)r.x * C2 + f2]));
        ax0 += w * v.x; ay0 += w * v.y;
    }
    float vx = (ax0 + ax1) + (ax2 + ax3);
    float vy = (ay0 + ay1) + (ay2 + ay3);
    if (bias) { vx += bias[2 * f2]; vy += bias[2 * f2 + 1]; }
    if (RELU) { vx = fmaxf(vx, 0.f); vy = fmaxf(vy, 0.f); }
    if (OUTF) {
        ((float2*)dstv)[(size_t)n * C2 + f2] = make_float2(vx, vy);
    } else {
        ((__half2*)dstv)[(size_t)n * C2 + f2] = __floats2half2_rn(vx, vy);
    }
}

// ================= shared GEMM primitives ==========
__device__ __forceinline__ void cp16(void* smem_dst, const void* gsrc) {
    unsigned d = (unsigned)__cvta_generic_to_shared(smem_dst);
    asm volatile("cp.async.cg.shared.global [%0], [%1], 16;" :: "r"(d), "l"(gsrc));
}
__device__ __forceinline__ void cp_commit() { asm volatile("cp.async.commit_group;"); }
__device__ __forceinline__ void cp_wait1() { asm volatile("cp.async.wait_group 1;"); }
__device__ __forceinline__ void cp_wait0() { asm volatile("cp.async.wait_group 0;"); }

__device__ __forceinline__ void ldsm4(unsigned& r0, unsigned& r1, unsigned& r2, unsigned& r3,
                                      const void* p) {
    unsigned a = (unsigned)__cvta_generic_to_shared(p);
    asm volatile("ldmatrix.sync.aligned.m8n8.x4.shared.b16 {%0,%1,%2,%3}, [%4];"
                 : "=r"(r0), "=r"(r1), "=r"(r2), "=r"(r3) : "r"(a));
}
__device__ __forceinline__ void ldsm4t(unsigned& r0, unsigned& r1, unsigned& r2, unsigned& r3,
                                       const void* p) {
    unsigned a = (unsigned)__cvta_generic_to_shared(p);
    asm volatile("ldmatrix.sync.aligned.m8n8.x4.trans.shared.b16 {%0,%1,%2,%3}, [%4];"
                 : "=r"(r0), "=r"(r1), "=r"(r2), "=r"(r3) : "r"(a));
}
__device__ __forceinline__ void mma16816(float* d, const unsigned* a, const unsigned* b) {
    asm volatile(
        "mma.sync.aligned.m16n8k16.row.col.f32.f16.f16.f32 "
        "{%0,%1,%2,%3},{%4,%5,%6,%7},{%8,%9},{%0,%1,%2,%3};\n"
        : "+f"(d[0]), "+f"(d[1]), "+f"(d[2]), "+f"(d[3])
        : "r"(a[0]), "r"(a[1]), "r"(a[2]), "r"(a[3]), "r"(b[0]), "r"(b[1]));
}

// ======== fused double GEMM: C = (relu(A@W0 + b0)) @ W1, N=256, K1 templated ========
#define FUSED_SMEM_HALVES (3 * 128 * 40 + 3 * 32 * 264 + 128 * 264)
#define FUSED_SMEM_BYTES  (FUSED_SMEM_HALVES * 2)

template<int K1, bool OUT8>
__global__ __launch_bounds__(256) void hgemm_fused(
    const __half* __restrict__ A, const __half* __restrict__ W0,
    const float* __restrict__ b0, const __half* __restrict__ W1,
    void* __restrict__ Cv, int M)
{
    extern __shared__ __half fsm[];
    __half (*As)[128][40] = (__half(*)[128][40])fsm;
    __half (*Bs)[32][264] = (__half(*)[32][264])(fsm + 3 * 128 * 40);
    __half (*Y1s)[264]    = (__half(*)[264])(fsm + 3 * 128 * 40 + 3 * 32 * 264);

    int tid = threadIdx.x;
    int bm = blockIdx.x * 128;
    int w = tid >> 5, lane = tid & 31;
    int wm = (w >> 2) * 64, wn = (w & 3) * 64;
    int lr16 = lane & 15, lh = lane >> 4;
    int lr = lane >> 2, lc = lane & 3;

    float acc[4][8][4];
#pragma unroll
    for (int mi = 0; mi < 4; ++mi)
#pragma unroll
        for (int nj = 0; nj < 8; ++nj)
#pragma unroll
            for (int q = 0; q < 4; ++q) acc[mi][nj][q] = 0.f;

#define LOAD_A_STAGE(st, k0) do {                                              \
    _Pragma("unroll")                                                          \
    for (int i = 0; i < 2; ++i) {                                              \
        int q = tid + i * 256;                                                 \
        int row = q >> 2, qc = (q & 3) * 8;                                    \
        cp16(&As[st][row][qc], A + (size_t)(bm + row) * K1 + (k0) + qc);       \
    }                                                                          \
    _Pragma("unroll")                                                          \
    for (int i = 0; i < 4; ++i) {                                              \
        int q = tid + i * 256;                                                 \
        int row = q >> 5, c8 = (q & 31) * 8;                                   \
        cp16(&Bs[st][row][c8], W0 + (size_t)((k0) + row) * 256 + c8);          \
    } } while (0)

#define LOAD_B_STAGE(st, k0) do {                                              \
    _Pragma("unroll")                                                          \
    for (int i = 0; i < 4; ++i) {                                              \
        int q = tid + i * 256;                                                 \
        int row = q >> 5, c8 = (q & 31) * 8;                                   \
        cp16(&Bs[st][row][c8], W1 + (size_t)((k0) + row) * 256 + c8);          \
    } } while (0)

    const int NS1 = K1 / 32;
    LOAD_A_STAGE(0, 0);
    cp_commit();
    if (NS1 > 1) LOAD_A_STAGE(1, 32);
    cp_commit();

    for (int s = 0; s < NS1; ++s) {
        int cur = s % 3;
        cp_wait1();
        __syncthreads();
        if (s + 2 < NS1) {
            int k0 = (s + 2) * 32;
            LOAD_A_STAGE((s + 2) % 3, k0);
        }
        cp_commit();
#pragma unroll
        for (int k16 = 0; k16 < 2; ++k16) {
            unsigned af[4][4], bf[8][2];
#pragma unroll
            for (int mi = 0; mi < 4; ++mi)
                ldsm4(af[mi][0], af[mi][1], af[mi][2], af[mi][3],
                      &As[cur][wm + mi * 16 + lr16][k16 * 16 + lh * 8]);
#pragma unroll
            for (int p = 0; p < 4; ++p) {
                unsigned r0, r1, r2, r3;
                ldsm4t(r0, r1, r2, r3, &Bs[cur][k16 * 16 + lr16][wn + p * 16 + lh * 8]);
                bf[2 * p][0] = r0; bf[2 * p][1] = r1;
                bf[2 * p + 1][0] = r2; bf[2 * p + 1][1] = r3;
            }
#pragma unroll
            for (int mi = 0; mi < 4; ++mi)
#pragma unroll
                for (int nj = 0; nj < 8; ++nj)
                    mma16816(acc[mi][nj], af[mi], bf[nj]);
        }
        __syncthreads();
    }
    cp_wait0();
    __syncthreads();

    // epilogue A: bias + relu -> Y1s (half)
#pragma unroll
    for (int mi = 0; mi < 4; ++mi) {
#pragma unroll
        for (int nj = 0; nj < 8; ++nj) {
            int row = wm + mi * 16 + lr;
            int col = wn + nj * 8 + 2 * lc;
            float2 bb = *(const float2*)(b0 + col);
            float v0 = fmaxf(acc[mi][nj][0] + bb.x, 0.f);
            float v1 = fmaxf(acc[mi][nj][1] + bb.y, 0.f);
            float v2 = fmaxf(acc[mi][nj][2] + bb.x, 0.f);
            float v3 = fmaxf(acc[mi][nj][3] + bb.y, 0.f);
            *(__half2*)&Y1s[row][col] = __floats2half2_rn(v0, v1);
            *(__half2*)&Y1s[row + 8][col] = __floats2half2_rn(v2, v3);
            acc[mi][nj][0] = 0.f; acc[mi][nj][1] = 0.f;
            acc[mi][nj][2] = 0.f; acc[mi][nj][3] = 0.f;
        }
    }
    __syncthreads();

    // stage B: Y2 = Y1s @ W1, K2 = 256
    LOAD_B_STAGE(0, 0);
    cp_commit();
    LOAD_B_STAGE(1, 32);
    cp_commit();

    for (int s = 0; s < 8; ++s) {
        int cur = s % 3;
        cp_wait1();
        __syncthreads();
        if (s + 2 < 8) {
            int k0 = (s + 2) * 32;
            LOAD_B_STAGE((s + 2) % 3, k0);
        }
        cp_commit();
#pragma unroll
        for (int k16 = 0; k16 < 2; ++k16) {
            unsigned af[4][4], bf[8][2];
#pragma unroll
            for (int mi = 0; mi < 4; ++mi)
                ldsm4(af[mi][0], af[mi][1], af[mi][2], af[mi][3],
                      &Y1s[wm + mi * 16 + lr16][s * 32 + k16 * 16 + lh * 8]);
#pragma unroll
            for (int p = 0; p < 4; ++p) {
                unsigned r0, r1, r2, r3;
                ldsm4t(r0, r1, r2, r3, &Bs[cur][k16 * 16 + lr16][wn + p * 16 + lh * 8]);
                bf[2 * p][0] = r0; bf[2 * p][1] = r1;
                bf[2 * p + 1][0] = r2; bf[2 * p + 1][1] = r3;
            }
#pragma unroll
            for (int mi = 0; mi < 4; ++mi)
#pragma unroll
                for (int nj = 0; nj < 8; ++nj)
                    mma16816(acc[mi][nj], af[mi], bf[nj]);
        }
        __syncthreads();
    }

    // epilogue B
#pragma unroll
    for (int mi = 0; mi < 4; ++mi) {
#pragma unroll
        for (int nj = 0; nj < 8; ++nj) {
            int row = bm + wm + mi * 16 + lr;
            int col = wn + nj * 8 + 2 * lc;
            if (OUT8) {
                unsigned char* C8 = (unsigned char*)Cv;
                *(unsigned short*)(C8 + (size_t)row * 256 + col) =
                    __nv_cvt_float2_to_fp8x2(make_float2(acc[mi][nj][0], acc[mi][nj][1]),
                                             __NV_SATFINITE, __NV_E4M3);
                *(unsigned short*)(C8 + (size_t)(row + 8) * 256 + col) =
                    __nv_cvt_float2_to_fp8x2(make_float2(acc[mi][nj][2], acc[mi][nj][3]),
                                             __NV_SATFINITE, __NV_E4M3);
            } else {
                __half* C = (__half*)Cv;
                *(__half2*)(C + (size_t)row * 256 + col) =
                    __floats2half2_rn(acc[mi][nj][0], acc[mi][nj][1]);
                *(__half2*)(C + (size_t)(row + 8) * 256 + col) =
                    __floats2half2_rn(acc[mi][nj][2], acc[mi][nj][3]);
            }
        }
    }
#undef LOAD_A_STAGE
#undef LOAD_B_STAGE
}

// ================= FP16 HMMA GEMM (decoder tail) with 3-stage cp.async pipeline ==========
template<bool HASBIAS, bool RELU>
__global__ __launch_bounds__(256) void hgemm(
    const __half* __restrict__ A, const __half* __restrict__ B,
    const float* __restrict__ bias, __half* __restrict__ C,
    int M, int K, int Ncols)
{
    __shared__ __align__(16) __half As[3][128][40];
    __shared__ __align__(16) __half Bs[3][32][136];
    int tid = threadIdx.x;
    int bm = blockIdx.x * 128, bn = blockIdx.y * 128;
    int w = tid >> 5, lane = tid & 31;
    int wm = (w >> 2) * 64, wn = (w & 3) * 32;
    int lr16 = lane & 15, lh = lane >> 4;

    float acc[4][4][4];
#pragma unroll
    for (int mi = 0; mi < 4; ++mi)
#pragma unroll
        for (int nj = 0; nj < 4; ++nj)
#pragma unroll
            for (int q = 0; q < 4; ++q) acc[mi][nj][q] = 0.f;

    int ar = tid >> 2, ac = (tid & 3) * 8;
    int br = tid >> 4, bc = (tid & 15) * 8;
    const __half* Ap = A + (size_t)(bm + ar) * K + ac;
    const __half* Bp = B + (size_t)br * Ncols + bn + bc;

    int nstage = K >> 5;
    cp16(&As[0][ar][ac], Ap);
    cp16(&As[0][ar + 64][ac], Ap + (size_t)64 * K);
    cp16(&Bs[0][br][bc], Bp);
    cp16(&Bs[0][br + 16][bc], Bp + (size_t)16 * Ncols);
    cp_commit();
    if (nstage > 1) {
        cp16(&As[1][ar][ac], Ap + 32);
        cp16(&As[1][ar + 64][ac], Ap + (size_t)64 * K + 32);
        cp16(&Bs[1][br][bc], Bp + (size_t)32 * Ncols);
        cp16(&Bs[1][br + 16][bc], Bp + (size_t)48 * Ncols);
    }
    cp_commit();

    for (int s = 0; s < nstage; ++s) {
        int cur = s % 3;
        cp_wait1();
        __syncthreads();
        if (s + 2 < nstage) {
            int k0 = (s + 2) << 5;
            int nxt = (s + 2) % 3;
            cp16(&As[nxt][ar][ac], Ap + k0);
            cp16(&As[nxt][ar + 64][ac], Ap + (size_t)64 * K + k0);
            cp16(&Bs[nxt][br][bc], Bp + (size_t)k0 * Ncols);
            cp16(&Bs[nxt][br + 16][bc], Bp + (size_t)(k0 + 16) * Ncols);
        }
        cp_commit();
#pragma unroll
        for (int k16 = 0; k16 < 2; ++k16) {
            unsigned af[4][4], bf[4][2];
#pragma unroll
            for (int mi = 0; mi < 4; ++mi)
                ldsm4(af[mi][0], af[mi][1], af[mi][2], af[mi][3],
                      &As[cur][wm + mi * 16 + lr16][k16 * 16 + lh * 8]);
#pragma unroll
            for (int p = 0; p < 2; ++p) {
                unsigned r0, r1, r2, r3;
                ldsm4t(r0, r1, r2, r3, &Bs[cur][k16 * 16 + lr16][wn + p * 16 + lh * 8]);
                bf[2 * p][0] = r0; bf[2 * p][1] = r1;
                bf[2 * p + 1][0] = r2; bf[2 * p + 1][1] = r3;
            }
#pragma unroll
            for (int mi = 0; mi < 4; ++mi)
#pragma unroll
                for (int nj = 0; nj < 4; ++nj)
                    mma16816(acc[mi][nj], af[mi], bf[nj]);
        }
    }

    __syncthreads();
    int lr = lane >> 2, lc = lane & 3;
#pragma unroll
    for (int mi = 0; mi < 4; ++mi) {
#pragma unroll
        for (int nj = 0; nj < 4; ++nj) {
            int row = bm + wm + mi * 16 + lr;
            int col = bn + wn + nj * 8 + 2 * lc;
            float b0 = 0.f, b1 = 0.f;
            if (HASBIAS) { b0 = bias[col]; b1 = bias[col + 1]; }
            float v0 = acc[mi][nj][0] + b0, v1 = acc[mi][nj][1] + b1;
            float v2 = acc[mi][nj][2] + b0, v3 = acc[mi][nj][3] + b1;
            if (RELU) {
                v0 = fmaxf(v0, 0.f); v1 = fmaxf(v1, 0.f);
                v2 = fmaxf(v2, 0.f); v3 = fmaxf(v3, 0.f);
            }
            *(__half2*)(C + (size_t)row * Ncols + col) = __floats2half2_rn(v0, v1);
            *(__half2*)(C + (size_t)(row + 8) * Ncols + col) = __floats2half2_rn(v2, v3);
        }
    }
}

// ---------------- z_t = g_t @ Wfce + bfce ----------------
__global__ __launch_bounds__(256) void proj_z_kernel(const float* __restrict__ Wfce,
                                                     const float* __restrict__ bfce) {
    __shared__ float part[256];
    int t = blockIdx.x;
    int tid = threadIdx.x;
    int j = tid & 63;
    int kq = tid >> 6;
    float a = 0.f;
#pragma unroll 8
    for (int k = kq * 64; k < kq * 64 + 64; ++k)
        a += d_gpool[t * HH + k] * __ldg(&Wfce[k * LL + j]);
    part[tid] = a;
    __syncthreads();
    if (tid < 64)
        d_zs[t * LL + tid] = part[tid] + part[64 + tid] + part[128 + tid] + part[192 + tid]
                             + bfce[tid];
}

// ---------------- persistent 2-layer LSTM + head: smem-resident fp16 weights ----------------
__device__ __forceinline__ float sigm(float x) { return 1.f / (1.f + expf(-x)); }

__device__ __forceinline__ void cluster_bar() {
    asm volatile("barrier.cluster.arrive.aligned;" ::: "memory");
    asm volatile("barrier.cluster.wait.aligned;" ::: "memory");
}

#define LSTM_SMEM_H2 (256 * 64 + 64 * 64 + 256 * 64 + 256 * 64)
#define LSTM_SMEM_BYTES (LSTM_SMEM_H2 * 4)

__global__ __launch_bounds__(256) __cluster_dims__(LSTM_BLOCKS, 1, 1) void lstm_kernel(
    const __half2* __restrict__ Wih0, const __half2* __restrict__ Whh0,
    const float* __restrict__ bih0, const float* __restrict__ bhh0,
    const __half2* __restrict__ Wih1, const __half2* __restrict__ Whh1,
    const float* __restrict__ bih1, const float* __restrict__ bhh1,
    const float* __restrict__ Whead, const float* __restrict__ bhead)
{
    extern __shared__ __half2 wsm[];
    __half2* whh0_s = wsm;
    __half2* wih0_s = whh0_s + 256 * 64;
    __half2* whh1_s = wih0_s + 64 * 64;
    __half2* wih1_s = whh1_s + 256 * 64;
    __shared__ float x_sh[LL];
    __shared__ float h1_sh[HL];
    __shared__ float h2_sh[HL];
    __shared__ float2 part[256];
    int tid = threadIdx.x;
    int b = blockIdx.x;
    int p = tid & 63;
    int kq = tid >> 6;
    float c1 = 0.f, c2 = 0.f;
    if (tid < HL) { h1_sh[tid] = 0.f; h2_sh[tid] = 0.f; }

    for (int i = tid; i < 256 * 64; i += 256) {
        int k = i >> 6, pp = i & 63;
        whh0_s[i] = Whh0[(size_t)k * 512 + b * 64 + pp];
        whh1_s[i] = Whh1[(size_t)k * 512 + b * 64 + pp];
        wih1_s[i] = Wih1[(size_t)k * 512 + b * 64 + pp];
    }
    for (int i = tid; i < 64 * 64; i += 256) {
        int k = i >> 6, pp = i & 63;
        wih0_s[i] = Wih0[(size_t)k * 512 + b * 64 + pp];
    }
    __syncthreads();
    int round = 0;

    for (int t = 0; t < TT; ++t) {
        if (tid < LL) x_sh[tid] = d_zs[t * LL + tid];
        __syncthreads();

        float ax = 0.f, ay = 0.f;
#pragma unroll 8
        for (int k = kq * 64; k < kq * 64 + 64; ++k) {
            float h = h1_sh[k];
            float2 w = __half22float2(whh0_s[k * 64 + p]);
            ax += h * w.x; ay += h * w.y;
        }
#pragma unroll 8
        for (int k = kq * 16; k < kq * 16 + 16; ++k) {
            float x = x_sh[k];
            float2 w = __half22float2(wih0_s[k * 64 + p]);
            ax += x * w.x; ay += x * w.y;
        }
        part[tid] = make_float2(ax, ay);
        __syncthreads();
        int pb = round & 1;
        if (tid < 64) {
            float2 a0 = part[tid], a1 = part[64 + tid], a2 = part[128 + tid], a3 = part[192 + tid];
            float2 bi = ((const float2*)bih0)[b * 64 + tid];
            float2 bh = ((const float2*)bhh0)[b * 64 + tid];
            float2 g = make_float2(a0.x + a1.x + a2.x + a3.x + bi.x + bh.x,
                                   a0.y + a1.y + a2.y + a3.y + bi.y + bh.y);
            __stcg(&((float2*)&d_gates[pb][0])[b * 64 + tid], g);
        }
        round++;
        __threadfence();
        cluster_bar();
        {
            float gi = __ldcg(&d_gates[pb][tid]);
            float gf = __ldcg(&d_gates[pb][256 + tid]);
            float gg = __ldcg(&d_gates[pb][512 + tid]);
            float go = __ldcg(&d_gates[pb][768 + tid]);
            c1 = sigm(gf) * c1 + sigm(gi) * tanhf(gg);
            h1_sh[tid] = sigm(go) * tanhf(c1);
        }
        __syncthreads();

        ax = 0.f; ay = 0.f;
#pragma unroll 8
        for (int k = kq * 64; k < kq * 64 + 64; ++k) {
            float h2v = h2_sh[k];
            float h1v = h1_sh[k];
            float2 wh = __half22float2(whh1_s[k * 64 + p]);
            float2 wi = __half22float2(wih1_s[k * 64 + p]);
            ax += h2v * wh.x + h1v * wi.x;
            ay += h2v * wh.y + h1v * wi.y;
        }
        part[tid] = make_float2(ax, ay);
        __syncthreads();
        pb = round & 1;
        if (tid < 64) {
            float2 a0 = part[tid], a1 = part[64 + tid], a2 = part[128 + tid], a3 = part[192 + tid];
            float2 bi = ((const float2*)bih1)[b * 64 + tid];
            float2 bh = ((const float2*)bhh1)[b * 64 + tid];
            float2 g = make_float2(a0.x + a1.x + a2.x + a3.x + bi.x + bh.x,
                                   a0.y + a1.y + a2.y + a3.y + bi.y + bh.y);
            __stcg(&((float2*)&d_gates[pb][0])[b * 64 + tid], g);
        }
        round++;
        __threadfence();
        cluster_bar();
        {
            float gi = __ldcg(&d_gates[pb][tid]);
            float gf = __ldcg(&d_gates[pb][256 + tid]);
            float gg = __ldcg(&d_gates[pb][512 + tid]);
            float go = __ldcg(&d_gates[pb][768 + tid]);
            c2 = sigm(gf) * c2 + sigm(gi) * tanhf(gg);
            h2_sh[tid] = sigm(go) * tanhf(c2);
        }
        __syncthreads();
    }

    if (b == 0 && tid < LL) {
        float a = bhead[tid];
        for (int k = 0; k < HL; ++k)
            a += h2_sh[k] * Whead[k * LL + tid];
        d_zfin[tid] = a;
    }
}

// ---------------- decoder fc: relu(z @ Wfcd + bfcd) -> half [N, L] ----------------
__global__ void fcd_kernel(const float* __restrict__ Wfcd, const float* __restrict__ bfcd,
                           __half2* __restrict__ out) {
    __shared__ float z[LL];
    if (threadIdx.x < LL) z[threadIdx.x] = d_zfin[threadIdx.x];
    __syncthreads();
    int q = blockIdx.x * blockDim.x + threadIdx.x;
    if (q >= NN * LL / 2) return;
    float2 bb = ((const float2*)bfcd)[q];
    float ax = bb.x, ay = bb.y;
#pragma unroll 8
    for (int k = 0; k < LL; ++k) {
        float2 w = ((const float2*)(Wfcd + (size_t)k * (NN * LL)))[q];
        ax += z[k] * w.x;
        ay += z[k] * w.y;
    }
    out[q] = __floats2half2_rn(fmaxf(ax, 0.f), fmaxf(ay, 0.f));
}

// ---------------- launch ----------------
extern "C" void kernel_launch(void* const* d_in, const int* in_sizes, int n_in,
                              void* d_out, int out_size) {
    const float* xs        = (const float*)d_in[0];
    const float* edge_attr = (const float*)d_in[1];
    const float* We0  = (const float*)d_in[2];
    const float* be0  = (const float*)d_in[3];
    const float* We1  = (const float*)d_in[4];
    const float* be1  = (const float*)d_in[5];
    const float* Wfce = (const float*)d_in[6];
    const float* bfce = (const float*)d_in[7];
    const float* Wih0 = (const float*)d_in[8];
    const float* Whh0 = (const float*)d_in[9];
    const float* bih0 = (const float*)d_in[10];
    const float* bhh0 = (const float*)d_in[11];
    const float* Wih1 = (const float*)d_in[12];
    const float* Whh1 = (const float*)d_in[13];
    const float* bih1 = (const float*)d_in[14];
    const float* bhh1 = (const float*)d_in[15];
    const float* Whead = (const float*)d_in[16];
    const float* bhead = (const float*)d_in[17];
    const float* Wfcd = (const float*)d_in[18];
    const float* bfcd = (const float*)d_in[19];
    const float* Wd0  = (const float*)d_in[20];
    const float* bd0  = (const float*)d_in[21];
    const float* Wd1  = (const float*)d_in[22];
    const float* bd1  = (const float*)d_in[23];
    const float* Wd2  = (const float*)d_in[24];
    const float* bd2  = (const float*)d_in[25];
    const void*  eidx = d_in[26];

    float *buf0, *buf1;
    __half *hbuf, *we0h, *we1h, *wd0h, *wd1h, *wd2h, *wih0h, *whh0h, *wih1h, *whh1h;
    unsigned char *x8, *h8;
    cudaGetSymbolAddress((void**)&buf0, d_buf0);
    cudaGetSymbolAddress((void**)&buf1, d_buf1);
    cudaGetSymbolAddress((void**)&hbuf, d_hbuf);
    cudaGetSymbolAddress((void**)&x8, d_x8);
    cudaGetSymbolAddress((void**)&h8, d_h8);
    cudaGetSymbolAddress((void**)&we0h, d_We0h);
    cudaGetSymbolAddress((void**)&we1h, d_We1h);
    cudaGetSymbolAddress((void**)&wd0h, d_Wd0h);
    cudaGetSymbolAddress((void**)&wd1h, d_Wd1h);
    cudaGetSymbolAddress((void**)&wd2h, d_Wd2h);
    cudaGetSymbolAddress((void**)&wih0h, d_Wih0h);
    cudaGetSymbolAddress((void**)&whh0h, d_Whh0h);
    cudaGetSymbolAddress((void**)&wih1h, d_Wih1h);
    cudaGetSymbolAddress((void**)&whh1h, d_Whh1h);

    const int MPAD = 10112;

    static cudaStream_t s2 = [](){ cudaStream_t t; cudaStreamCreateWithFlags(&t, cudaStreamNonBlocking); return t; }();
    static cudaEvent_t evFork = [](){ cudaEvent_t e; cudaEventCreateWithFlags(&e, cudaEventDisableTiming); return e; }();
    static cudaEvent_t evJoin = [](){ cudaEvent_t e; cudaEventCreateWithFlags(&e, cudaEventDisableTiming); return e; }();
    static cudaEvent_t evMid  = [](){ cudaEvent_t e; cudaEventCreateWithFlags(&e, cudaEventDisableTiming); return e; }();
    static cudaEvent_t evJoin2 = [](){ cudaEvent_t e; cudaEventCreateWithFlags(&e, cudaEventDisableTiming); return e; }();
    static bool attrSet = [](){
        cudaFuncSetAttribute(lstm_kernel, cudaFuncAttributeMaxDynamicSharedMemorySize, LSTM_SMEM_BYTES);
        cudaFuncSetAttribute(hgemm_fused<128, true>, cudaFuncAttributeMaxDynamicSharedMemorySize, FUSED_SMEM_BYTES);
        cudaFuncSetAttribute(hgemm_fused<64, false>, cudaFuncAttributeMaxDynamicSharedMemorySize, FUSED_SMEM_BYTES);
        return true;
    }();
    (void)attrSet;

    cudaEventRecord(evFork, 0);
    cudaStreamWaitEvent(s2, evFork, 0);
    f2h_all_kernel<<<(N2_TOT + 255) / 256, 256, 0, s2>>>(
        xs, We0, We1, Wd0, Wd1, Wd2, Wih0, Whh0, Wih1, Whh1,
        (unsigned short*)x8, (__half2*)we0h, (__half2*)we1h,
        (__half2*)wd0h, (__half2*)wd1h, (__half2*)wd2h,
        (__half2*)wih0h, (__half2*)whh0h, (__half2*)wih1h, (__half2*)whh1h);
    cudaEventRecord(evJoin, s2);

    // ---- preprocessing (main stream) ----
    zero_kernel<<<(NN + 255) / 256, 256>>>(eidx);
    count_kernel<<<(EN + 255) / 256, 256>>>(eidx, edge_attr);
    scanA_kernel<<<10, 1024>>>();
    scanC_kernel<<<10, 1024>>>();
    fill_kernel<<<(EN + 255) / 256, 256>>>(eidx, edge_attr);

    cudaStreamWaitEvent(0, evJoin, 0);

    // ---- encoder (fp8 gathers, fused double GEMM) ----
    agg_enc0_kernel<<<NN, 128>>>((const uint4*)x8, (uint4*)buf0);
    hgemm_fused<128, true><<<TT * NN / 128, 256, FUSED_SMEM_BYTES>>>(
        (const __half*)buf0, we0h, be0, we1h, h8, TT * NN);
    agg_pool_kernel<<<1250, 256>>>((const uint4*)h8, be1);
    proj_z_kernel<<<TT, 256>>>(Wfce, bfce);

    // fork: warm first 96MB of Wfcd into L2 while the LSTM runs on 8 SMs
    cudaEventRecord(evMid, 0);
    cudaStreamWaitEvent(s2, evMid, 0);
    prefetch_kernel<<<1024, 256, 0, s2>>>((const float4*)Wfcd, 6291456);
    cudaEventRecord(evJoin2, s2);

    // ---- LSTM + head (smem-resident weights) ----
    lstm_kernel<<<LSTM_BLOCKS, 256, LSTM_SMEM_BYTES>>>(
        (const __half2*)wih0h, (const __half2*)whh0h, bih0, bhh0,
        (const __half2*)wih1h, (const __half2*)whh1h, bih1, bhh1, Whead, bhead);

    cudaStreamWaitEvent(0, evJoin2, 0);

    // ---- decoder (fp16, fused first GEMM pair) ----
    fcd_kernel<<<(NN * LL / 2 + 255) / 256, 256>>>(Wfcd, bfcd, (__half2*)hbuf);
    agg_dec_kernel<LL / 2, 4, false, false><<<(NN + 3) / 4, 128>>>(
        (const __half2*)hbuf, (__half*)buf0, nullptr);
    hgemm_fused<64, false><<<MPAD / 128, 256, FUSED_SMEM_BYTES>>>(
        (const __half*)buf0, wd0h, bd0, wd1h, hbuf, MPAD);
    agg_dec_kernel<HH / 2, 2, true, false><<<(NN + 1) / 2, 256>>>(
        (const __half2*)hbuf, (__half*)buf0, bd1);
    hgemm<false, false><<<dim3(MPAD / 128, FF / 128), 256>>>(
        (const __half*)buf0, wd2h, nullptr, (__half*)buf1, MPAD, HH, FF);
    agg_dec_kernel<FF / 2, 2, false, true><<<(NN + 1) / 2, 128>>>(
        (const __half2*)buf1, (float*)d_out, bd2);
}

// round 17
// speedup vs baseline: 1.0096x; 1.0096x over previous
#include <cuda_runtime.h>
#include <cuda_fp16.h>
#include <cuda_fp8.h>
#include <cuda_bf16.h>
#include <math.h>

#define TT 16
#define NN 10000
#define EE 320000
#define EN (EE + NN)
#define FF 128
#define HH 256
#define LL 64
#define HL 256
#define LSTM_BLOCKS 8

// ---------------- device scratch ----------------
__device__ int   d_rowptr[NN + 1];
__device__ int   d_cnt[NN];
__device__ int   d_bsum[10];
__device__ int   d_col[EN];
__device__ float d_nrm_enc[EN];
__device__ float d_nrm_dec[EN];
__device__ float d_deg_enc[NN];
__device__ float d_deg_dec[NN];
__device__ float d_dis_enc[NN];
__device__ float d_dis_dec[NN];
__device__ __align__(16) float d_buf0[(size_t)TT * NN * HH];
__device__ __align__(16) float d_buf1[(size_t)TT * NN * HH];
__device__ __align__(16) __half d_hbuf[(size_t)TT * NN * HH];
__device__ __align__(16) unsigned char d_x8[(size_t)TT * NN * FF];   // xs in e4m3
__device__ __align__(16) unsigned char d_h8[(size_t)TT * NN * HH];   // fused GEMM out in e4m3
__device__ __align__(16) __half d_We0h[FF * HH];
__device__ __align__(16) __half d_We1h[HH * HH];
__device__ __align__(16) __half d_Wd0h[LL * HH];
__device__ __align__(16) __half d_Wd1h[HH * HH];
__device__ __align__(16) __half d_Wd2h[HH * FF];
__device__ __align__(16) __half d_Wih0h[LL * 4 * HL];
__device__ __align__(16) __half d_Whh0h[HL * 4 * HL];
__device__ __align__(16) __half d_Wih1h[HL * 4 * HL];
__device__ __align__(16) __half d_Whh1h[HL * 4 * HL];
__device__ float d_gpool[TT * HH];
__device__ float d_zs[TT * LL];
__device__ __align__(16) float d_gates[2][4 * HL];
__device__ float d_zfin[LL];
__device__ float d_sink;
__device__ int   d_idx64;

__device__ __forceinline__ void get_edge(const void* ei, int e, int& s, int& d) {
    if (d_idx64) {
        const long long* p = (const long long*)ei;
        s = (int)p[e];
        d = (int)p[EE + e];
    } else {
        const int* p = (const int*)ei;
        s = p[e];
        d = p[EE + e];
    }
}

// ---------------- preprocessing ----------------
__global__ void detect_kernel(const void* ei) {
    if (threadIdx.x == 0) {
        const unsigned int* w = (const unsigned int*)ei;
        int is64 = 1;
        for (int k = 0; k < 64; ++k)
            if (w[2 * k + 1] != 0u) { is64 = 0; break; }
        d_idx64 = is64;
    }
}

__global__ void count_kernel(const void* ei, const float* __restrict__ ea) {
    int e = blockIdx.x * blockDim.x + threadIdx.x;
    if (e >= EN) return;
    int s, d; float w;
    if (e < EE) { get_edge(ei, e, s, d); w = ea[e]; }
    else { s = d = e - EE; w = 1.f; }
    atomicAdd(&d_deg_enc[d], w);
    atomicAdd(&d_deg_dec[d], 1.f);
}

__global__ __launch_bounds__(1024) void scanA_kernel() {
    __shared__ int sh[1024];
    int blk = blockIdx.x, tid = threadIdx.x;
    int idx = blk * 1000 + tid;
    int c = (tid < 1000) ? (int)d_deg_dec[idx] : 0;
    sh[tid] = c;
    __syncthreads();
    for (int off = 1; off < 1024; off <<= 1) {
        int v = (tid >= off) ? sh[tid - off] : 0;
        __syncthreads();
        sh[tid] += v;
        __syncthreads();
    }
    if (tid < 1000) {
        d_rowptr[idx] = sh[tid] - c;
        d_dis_enc[idx] = rsqrtf(d_deg_enc[idx]);
        d_dis_dec[idx] = rsqrtf(d_deg_dec[idx]);
    }
    if (tid == 1023) d_bsum[blk] = sh[1023];
}

__global__ __launch_bounds__(1024) void scanC_kernel() {
    __shared__ int off_sh;
    int blk = blockIdx.x, tid = threadIdx.x;
    if (tid == 0) {
        int o = 0;
        for (int i = 0; i < blk; ++i) o += d_bsum[i];
        off_sh = o;
        if (blk == 9) d_rowptr[NN] = o + d_bsum[9];
    }
    __syncthreads();
    int idx = blk * 1000 + tid;
    if (tid < 1000) d_rowptr[idx] += off_sh;
}

__global__ void fill_kernel(const void* ei, const float* __restrict__ ea) {
    int e = blockIdx.x * blockDim.x + threadIdx.x;
    if (e >= EN) return;
    int s, d; float w;
    if (e < EE) { get_edge(ei, e, s, d); w = ea[e]; }
    else { s = d = e - EE; w = 1.f; }
    int pos = d_rowptr[d] + atomicAdd(&d_cnt[d], 1);
    d_col[pos] = s;
    d_nrm_enc[pos] = d_dis_enc[s] * w * d_dis_enc[d];
    d_nrm_dec[pos] = d_dis_dec[s] * d_dis_dec[d];
}

// ---------------- L2 prefetch (warms Wfcd during LSTM) ----------------
__global__ void prefetch_kernel(const float4* __restrict__ p, int n4) {
    float acc = 0.f;
    for (int i = blockIdx.x * blockDim.x + threadIdx.x; i < n4; i += gridDim.x * blockDim.x) {
        float4 v = __ldg(p + i);
        acc += v.x + v.y + v.z + v.w;
    }
    if (acc == 1.234567e30f) d_sink = acc;
}

// ---------------- fused conversions: xs -> fp8, all weights -> fp16 ----------------
#define N2_XS    (TT * NN * FF / 2)
#define N2_WE0   (FF * HH / 2)
#define N2_WE1   (HH * HH / 2)
#define N2_WD0   (LL * HH / 2)
#define N2_WD1   (HH * HH / 2)
#define N2_WD2   (HH * FF / 2)
#define N2_WIH0  (LL * 4 * HL / 2)
#define N2_WHH0  (HL * 4 * HL / 2)
#define N2_WIH1  (HL * 4 * HL / 2)
#define N2_WHH1  (HL * 4 * HL / 2)
#define N2_TOT   (N2_XS + N2_WE0 + N2_WE1 + N2_WD0 + N2_WD1 + N2_WD2 + \
                  N2_WIH0 + N2_WHH0 + N2_WIH1 + N2_WHH1)

__global__ void f2h_all_kernel(const float* xs, const float* We0, const float* We1,
                               const float* Wd0, const float* Wd1, const float* Wd2,
                               const float* Wih0, const float* Whh0,
                               const float* Wih1, const float* Whh1,
                               unsigned short* hx8, __half2* hwe0, __half2* hwe1,
                               __half2* hwd0, __half2* hwd1, __half2* hwd2,
                               __half2* hwih0, __half2* hwhh0,
                               __half2* hwih1, __half2* hwhh1) {
    int i = blockIdx.x * blockDim.x + threadIdx.x;
    int off = i;
    if (off < N2_XS) {
        float2 v = ((const float2*)xs)[off];
        hx8[off] = __nv_cvt_float2_to_fp8x2(v, __NV_SATFINITE, __NV_E4M3);
        return;
    }
    const float* src; __half2* dst;
    off -= N2_XS;
    if (off < N2_WE0) { src = We0; dst = hwe0; }
    else if ((off -= N2_WE0) < N2_WE1) { src = We1; dst = hwe1; }
    else if ((off -= N2_WE1) < N2_WD0) { src = Wd0; dst = hwd0; }
    else if ((off -= N2_WD0) < N2_WD1) { src = Wd1; dst = hwd1; }
    else if ((off -= N2_WD1) < N2_WD2) { src = Wd2; dst = hwd2; }
    else if ((off -= N2_WD2) < N2_WIH0) { src = Wih0; dst = hwih0; }
    else if ((off -= N2_WIH0) < N2_WHH0) { src = Whh0; dst = hwhh0; }
    else if ((off -= N2_WHH0) < N2_WIH1) { src = Wih1; dst = hwih1; }
    else if ((off -= N2_WIH1) < N2_WHH1) { src = Whh1; dst = hwhh1; }
    else return;
    float2 v = ((const float2*)src)[off];
    dst[off] = __floats2half2_rn(v.x, v.y);
}

// ---------------- fp8x2 -> half2 ----------------
__device__ __forceinline__ __half2 fp8x2_h2(unsigned short s) {
    __half2_raw hr = __nv_cvt_fp8x2_to_halfraw2((__nv_fp8x2_storage_t)s, __NV_E4M3);
    return *(__half2*)&hr;
}

// ---------------- encoder layer0 agg: fp8 gathers, HFMA2 accumulate, half2 out ----------------
__global__ __launch_bounds__(128) void agg_enc0_kernel(const uint4* __restrict__ src,
                                                       uint4* __restrict__ dst) {
    int n = blockIdx.x;
    int tid = threadIdx.x;
    int f4 = tid & 7;
    int ts = tid >> 3;
    int beg = d_rowptr[n], end = d_rowptr[n + 1];
    size_t pb = (size_t)ts * NN * 8;
    __half2 acc[8];
#pragma unroll
    for (int i = 0; i < 8; ++i) acc[i] = __floats2half2_rn(0.f, 0.f);
    int e = beg;
    for (; e + 2 <= end; e += 2) {
        int s0 = __ldg(&d_col[e]);
        int s1 = __ldg(&d_col[e + 1]);
        float w0 = __ldg(&d_nrm_enc[e]);
        float w1 = __ldg(&d_nrm_enc[e + 1]);
        __half2 w02 = __floats2half2_rn(w0, w0);
        __half2 w12 = __floats2half2_rn(w1, w1);
        uint4 v0 = __ldg(src + pb + (size_t)s0 * 8 + f4);
        uint4 v1 = __ldg(src + pb + (size_t)s1 * 8 + f4);
        const unsigned short* p0 = (const unsigned short*)&v0;
        const unsigned short* p1 = (const unsigned short*)&v1;
#pragma unroll
        for (int p = 0; p < 8; ++p) {
            acc[p] = __hfma2(fp8x2_h2(p0[p]), w02, acc[p]);
            acc[p] = __hfma2(fp8x2_h2(p1[p]), w12, acc[p]);
        }
    }
    if (e < end) {
        int s = __ldg(&d_col[e]);
        float w = __ldg(&d_nrm_enc[e]);
        __half2 w2 = __floats2half2_rn(w, w);
        uint4 v = __ldg(src + pb + (size_t)s * 8 + f4);
        const unsigned short* p = (const unsigned short*)&v;
#pragma unroll
        for (int q = 0; q < 8; ++q)
            acc[q] = __hfma2(fp8x2_h2(p[q]), w2, acc[q]);
    }
    uint4 o[2];
    __half2* oh = (__half2*)o;
#pragma unroll
    for (int p = 0; p < 8; ++p) oh[p] = acc[p];
    uint4* dp = dst + ((size_t)ts * NN + n) * 16 + f4 * 2;
    dp[0] = o[0];
    dp[1] = o[1];
}

// ---------------- agg + bias + relu + mean-pool: fp8 gathers, HFMA2, 8 nodes/block ----------------
__global__ __launch_bounds__(256) void agg_pool_kernel(const uint4* __restrict__ src,
                                                       const float* __restrict__ bias) {
    int tid = threadIdx.x;
    int f4 = tid & 15;
    int ts = tid >> 4;
    int n0 = blockIdx.x * 8;
    float b[16];
#pragma unroll
    for (int i = 0; i < 16; ++i) b[i] = bias[f4 * 16 + i];
    float pool[16];
#pragma unroll
    for (int i = 0; i < 16; ++i) pool[i] = 0.f;
    size_t pb = (size_t)ts * NN * 16;
    for (int n = n0; n < n0 + 8; ++n) {
        int beg = d_rowptr[n], end = d_rowptr[n + 1];
        __half2 acc[8];
#pragma unroll
        for (int i = 0; i < 8; ++i) acc[i] = __floats2half2_rn(0.f, 0.f);
        int e = beg;
        for (; e + 2 <= end; e += 2) {
            int s0 = __ldg(&d_col[e]);
            int s1 = __ldg(&d_col[e + 1]);
            float w0 = __ldg(&d_nrm_enc[e]);
            float w1 = __ldg(&d_nrm_enc[e + 1]);
            __half2 w02 = __floats2half2_rn(w0, w0);
            __half2 w12 = __floats2half2_rn(w1, w1);
            uint4 v0 = __ldg(src + pb + (size_t)s0 * 16 + f4);
            uint4 v1 = __ldg(src + pb + (size_t)s1 * 16 + f4);
            const unsigned short* p0 = (const unsigned short*)&v0;
            const unsigned short* p1 = (const unsigned short*)&v1;
#pragma unroll
            for (int p = 0; p < 8; ++p) {
                acc[p] = __hfma2(fp8x2_h2(p0[p]), w02, acc[p]);
                acc[p] = __hfma2(fp8x2_h2(p1[p]), w12, acc[p]);
            }
        }
        if (e < end) {
            int s = __ldg(&d_col[e]);
            float w = __ldg(&d_nrm_enc[e]);
            __half2 w2 = __floats2half2_rn(w, w);
            uint4 v = __ldg(src + pb + (size_t)s * 16 + f4);
            const unsigned short* p = (const unsigned short*)&v;
#pragma unroll
            for (int q = 0; q < 8; ++q)
                acc[q] = __hfma2(fp8x2_h2(p[q]), w2, acc[q]);
        }
#pragma unroll
        for (int i = 0; i < 8; ++i) {
            float2 f = __half22float2(acc[i]);
            pool[2 * i]     += fmaxf(f.x + b[2 * i], 0.f);
            pool[2 * i + 1] += fmaxf(f.y + b[2 * i + 1], 0.f);
        }
    }
#pragma unroll
    for (int i = 0; i < 16; ++i)
        atomicAdd(&d_gpool[ts * HH + f4 * 16 + i], pool[i] * (1.0f / NN));
}

// ---------------- decoder CSR aggregation (fp16 src, fp32 accum): warp-aligned nodes ----------------
template<int C2, int NPB, bool RELU, bool OUTF>
__global__ void agg_dec_kernel(const __half2* __restrict__ src, void* __restrict__ dstv,
                               const float* __restrict__ bias) {
    int tid = threadIdx.x;
    int n = blockIdx.x * NPB + tid / C2;
    int f2 = tid % C2;
    if (n >= NN) return;
    int beg = d_rowptr[n], end = d_rowptr[n + 1];
    float ax0 = 0.f, ay0 = 0.f, ax1 = 0.f, ay1 = 0.f;
    float ax2 = 0.f, ay2 = 0.f, ax3 = 0.f, ay3 = 0.f;
    int e = beg;
    for (; e + 4 <= end; e += 4) {
        int s0 = __ldg(&d_col[e]);
        int s1 = __ldg(&d_col[e + 1]);
        int s2 = __ldg(&d_col[e + 2]);
        int s3 = __ldg(&d_col[e + 3]);
        float w0 = __ldg(&d_nrm_dec[e]);
        float w1 = __ldg(&d_nrm_dec[e + 1]);
        float w2 = __ldg(&d_nrm_dec[e + 2]);
        float w3 = __ldg(&d_nrm_dec[e + 3]);
        float2 v0 = __half22float2(__ldg(&src[(size_t)s0 * C2 + f2]));
        float2 v1 = __half22float2(__ldg(&src[(size_t)s1 * C2 + f2]));
        float2 v2 = __half22float2(__ldg(&src[(size_t)s2 * C2 + f2]));
        float2 v3 = __half22float2(__ldg(&src[(size_t)s3 * C2 + f2]));
        ax0 += w0 * v0.x; ay0 += w0 * v0.y;
        ax1 += w1 * v1.x; ay1 += w1 * v1.y;
        ax2 += w2 * v2.x; ay2 += w2 * v2.y;
        ax3 += w3 * v3.x; ay3 += w3 * v3.y;
    }
    for (; e < end; ++e) {
        int s = __ldg(&d_col[e]);
        float w = __ldg(&d_nrm_dec[e]);
        float2 v = __half22float2(__ldg(&src[(size_t)s * C2 + f2]));
        ax0 += w * v.x; ay0 += w * v.y;
    }
    float vx = (ax0 + ax1) + (ax2 + ax3);
    float vy = (ay0 + ay1) + (ay2 + ay3);
    if (bias) { vx += bias[2 * f2]; vy += bias[2 * f2 + 1]; }
    if (RELU) { vx = fmaxf(vx, 0.f); vy = fmaxf(vy, 0.f); }
    if (OUTF) {
        ((float2*)dstv)[(size_t)n * C2 + f2] = make_float2(vx, vy);
    } else {
        ((__half2*)dstv)[(size_t)n * C2 + f2] = __floats2half2_rn(vx, vy);
    }
}

// ================= shared GEMM primitives ==========
__device__ __forceinline__ void cp16(void* smem_dst, const void* gsrc) {
    unsigned d = (unsigned)__cvta_generic_to_shared(smem_dst);
    asm volatile("cp.async.cg.shared.global [%0], [%1], 16;" :: "r"(d), "l"(gsrc));
}
__device__ __forceinline__ void cp_commit() { asm volatile("cp.async.commit_group;"); }
__device__ __forceinline__ void cp_wait1() { asm volatile("cp.async.wait_group 1;"); }
__device__ __forceinline__ void cp_wait0() { asm volatile("cp.async.wait_group 0;"); }

__device__ __forceinline__ void ldsm4(unsigned& r0, unsigned& r1, unsigned& r2, unsigned& r3,
                                      const void* p) {
    unsigned a = (unsigned)__cvta_generic_to_shared(p);
    asm volatile("ldmatrix.sync.aligned.m8n8.x4.shared.b16 {%0,%1,%2,%3}, [%4];"
                 : "=r"(r0), "=r"(r1), "=r"(r2), "=r"(r3) : "r"(a));
}
__device__ __forceinline__ void ldsm4t(unsigned& r0, unsigned& r1, unsigned& r2, unsigned& r3,
                                       const void* p) {
    unsigned a = (unsigned)__cvta_generic_to_shared(p);
    asm volatile("ldmatrix.sync.aligned.m8n8.x4.trans.shared.b16 {%0,%1,%2,%3}, [%4];"
                 : "=r"(r0), "=r"(r1), "=r"(r2), "=r"(r3) : "r"(a));
}
__device__ __forceinline__ void mma16816(float* d, const unsigned* a, const unsigned* b) {
    asm volatile(
        "mma.sync.aligned.m16n8k16.row.col.f32.f16.f16.f32 "
        "{%0,%1,%2,%3},{%4,%5,%6,%7},{%8,%9},{%0,%1,%2,%3};\n"
        : "+f"(d[0]), "+f"(d[1]), "+f"(d[2]), "+f"(d[3])
        : "r"(a[0]), "r"(a[1]), "r"(a[2]), "r"(a[3]), "r"(b[0]), "r"(b[1]));
}

// ======== fused double GEMM: C = (relu(A@W0 + b0)) @ W1, N=256, K1 templated ========
#define FUSED_SMEM_HALVES (3 * 128 * 40 + 3 * 32 * 264 + 128 * 264)
#define FUSED_SMEM_BYTES  (FUSED_SMEM_HALVES * 2)

template<int K1, bool OUT8>
__global__ __launch_bounds__(256) void hgemm_fused(
    const __half* __restrict__ A, const __half* __restrict__ W0,
    const float* __restrict__ b0, const __half* __restrict__ W1,
    void* __restrict__ Cv, int M)
{
    extern __shared__ __half fsm[];
    __half (*As)[128][40] = (__half(*)[128][40])fsm;
    __half (*Bs)[32][264] = (__half(*)[32][264])(fsm + 3 * 128 * 40);
    __half (*Y1s)[264]    = (__half(*)[264])(fsm + 3 * 128 * 40 + 3 * 32 * 264);

    int tid = threadIdx.x;
    int bm = blockIdx.x * 128;
    int w = tid >> 5, lane = tid & 31;
    int wm = (w >> 2) * 64, wn = (w & 3) * 64;
    int lr16 = lane & 15, lh = lane >> 4;
    int lr = lane >> 2, lc = lane & 3;

    float acc[4][8][4];
#pragma unroll
    for (int mi = 0; mi < 4; ++mi)
#pragma unroll
        for (int nj = 0; nj < 8; ++nj)
#pragma unroll
            for (int q = 0; q < 4; ++q) acc[mi][nj][q] = 0.f;

#define LOAD_A_STAGE(st, k0) do {                                              \
    _Pragma("unroll")                                                          \
    for (int i = 0; i < 2; ++i) {                                              \
        int q = tid + i * 256;                                                 \
        int row = q >> 2, qc = (q & 3) * 8;                                    \
        cp16(&As[st][row][qc], A + (size_t)(bm + row) * K1 + (k0) + qc);       \
    }                                                                          \
    _Pragma("unroll")                                                          \
    for (int i = 0; i < 4; ++i) {                                              \
        int q = tid + i * 256;                                                 \
        int row = q >> 5, c8 = (q & 31) * 8;                                   \
        cp16(&Bs[st][row][c8], W0 + (size_t)((k0) + row) * 256 + c8);          \
    } } while (0)

#define LOAD_B_STAGE(st, k0) do {                                              \
    _Pragma("unroll")                                                          \
    for (int i = 0; i < 4; ++i) {                                              \
        int q = tid + i * 256;                                                 \
        int row = q >> 5, c8 = (q & 31) * 8;                                   \
        cp16(&Bs[st][row][c8], W1 + (size_t)((k0) + row) * 256 + c8);          \
    } } while (0)

    const int NS1 = K1 / 32;
    LOAD_A_STAGE(0, 0);
    cp_commit();
    if (NS1 > 1) LOAD_A_STAGE(1, 32);
    cp_commit();

    for (int s = 0; s < NS1; ++s) {
        int cur = s % 3;
        cp_wait1();
        __syncthreads();
        if (s + 2 < NS1) {
            int k0 = (s + 2) * 32;
            LOAD_A_STAGE((s + 2) % 3, k0);
        }
        cp_commit();
#pragma unroll
        for (int k16 = 0; k16 < 2; ++k16) {
            unsigned af[4][4], bf[8][2];
#pragma unroll
            for (int mi = 0; mi < 4; ++mi)
                ldsm4(af[mi][0], af[mi][1], af[mi][2], af[mi][3],
                      &As[cur][wm + mi * 16 + lr16][k16 * 16 + lh * 8]);
#pragma unroll
            for (int p = 0; p < 4; ++p) {
                unsigned r0, r1, r2, r3;
                ldsm4t(r0, r1, r2, r3, &Bs[cur][k16 * 16 + lr16][wn + p * 16 + lh * 8]);
                bf[2 * p][0] = r0; bf[2 * p][1] = r1;
                bf[2 * p + 1][0] = r2; bf[2 * p + 1][1] = r3;
            }
#pragma unroll
            for (int mi = 0; mi < 4; ++mi)
#pragma unroll
                for (int nj = 0; nj < 8; ++nj)
                    mma16816(acc[mi][nj], af[mi], bf[nj]);
        }
        __syncthreads();
    }
    cp_wait0();
    __syncthreads();

    // epilogue A: bias + relu -> Y1s (half)
#pragma unroll
    for (int mi = 0; mi < 4; ++mi) {
#pragma unroll
        for (int nj = 0; nj < 8; ++nj) {
            int row = wm + mi * 16 + lr;
            int col = wn + nj * 8 + 2 * lc;
            float2 bb = *(const float2*)(b0 + col);
            float v0 = fmaxf(acc[mi][nj][0] + bb.x, 0.f);
            float v1 = fmaxf(acc[mi][nj][1] + bb.y, 0.f);
            float v2 = fmaxf(acc[mi][nj][2] + bb.x, 0.f);
            float v3 = fmaxf(acc[mi][nj][3] + bb.y, 0.f);
            *(__half2*)&Y1s[row][col] = __floats2half2_rn(v0, v1);
            *(__half2*)&Y1s[row + 8][col] = __floats2half2_rn(v2, v3);
            acc[mi][nj][0] = 0.f; acc[mi][nj][1] = 0.f;
            acc[mi][nj][2] = 0.f; acc[mi][nj][3] = 0.f;
        }
    }
    __syncthreads();

    // stage B: Y2 = Y1s @ W1, K2 = 256
    LOAD_B_STAGE(0, 0);
    cp_commit();
    LOAD_B_STAGE(1, 32);
    cp_commit();

    for (int s = 0; s < 8; ++s) {
        int cur = s % 3;
        cp_wait1();
        __syncthreads();
        if (s + 2 < 8) {
            int k0 = (s + 2) * 32;
            LOAD_B_STAGE((s + 2) % 3, k0);
        }
        cp_commit();
#pragma unroll
        for (int k16 = 0; k16 < 2; ++k16) {
            unsigned af[4][4], bf[8][2];
#pragma unroll
            for (int mi = 0; mi < 4; ++mi)
                ldsm4(af[mi][0], af[mi][1], af[mi][2], af[mi][3],
                      &Y1s[wm + mi * 16 + lr16][s * 32 + k16 * 16 + lh * 8]);
#pragma unroll
            for (int p = 0; p < 4; ++p) {
                unsigned r0, r1, r2, r3;
                ldsm4t(r0, r1, r2, r3, &Bs[cur][k16 * 16 + lr16][wn + p * 16 + lh * 8]);
                bf[2 * p][0] = r0; bf[2 * p][1] = r1;
                bf[2 * p + 1][0] = r2; bf[2 * p + 1][1] = r3;
            }
#pragma unroll
            for (int mi = 0; mi < 4; ++mi)
#pragma unroll
                for (int nj = 0; nj < 8; ++nj)
                    mma16816(acc[mi][nj], af[mi], bf[nj]);
        }
        __syncthreads();
    }

    // epilogue B
#pragma unroll
    for (int mi = 0; mi < 4; ++mi) {
#pragma unroll
        for (int nj = 0; nj < 8; ++nj) {
            int row = bm + wm + mi * 16 + lr;
            int col = wn + nj * 8 + 2 * lc;
            if (OUT8) {
                unsigned char* C8 = (unsigned char*)Cv;
                *(unsigned short*)(C8 + (size_t)row * 256 + col) =
                    __nv_cvt_float2_to_fp8x2(make_float2(acc[mi][nj][0], acc[mi][nj][1]),
                                             __NV_SATFINITE, __NV_E4M3);
                *(unsigned short*)(C8 + (size_t)(row + 8) * 256 + col) =
                    __nv_cvt_float2_to_fp8x2(make_float2(acc[mi][nj][2], acc[mi][nj][3]),
                                             __NV_SATFINITE, __NV_E4M3);
            } else {
                __half* C = (__half*)Cv;
                *(__half2*)(C + (size_t)row * 256 + col) =
                    __floats2half2_rn(acc[mi][nj][0], acc[mi][nj][1]);
                *(__half2*)(C + (size_t)(row + 8) * 256 + col) =
                    __floats2half2_rn(acc[mi][nj][2], acc[mi][nj][3]);
            }
        }
    }
#undef LOAD_A_STAGE
#undef LOAD_B_STAGE
}

// ================= FP16 HMMA GEMM (decoder tail) with 3-stage cp.async pipeline ==========
template<bool HASBIAS, bool RELU>
__global__ __launch_bounds__(256) void hgemm(
    const __half* __restrict__ A, const __half* __restrict__ B,
    const float* __restrict__ bias, __half* __restrict__ C,
    int M, int K, int Ncols)
{
    __shared__ __align__(16) __half As[3][128][40];
    __shared__ __align__(16) __half Bs[3][32][136];
    int tid = threadIdx.x;
    int bm = blockIdx.x * 128, bn = blockIdx.y * 128;
    int w = tid >> 5, lane = tid & 31;
    int wm = (w >> 2) * 64, wn = (w & 3) * 32;
    int lr16 = lane & 15, lh = lane >> 4;

    float acc[4][4][4];
#pragma unroll
    for (int mi = 0; mi < 4; ++mi)
#pragma unroll
        for (int nj = 0; nj < 4; ++nj)
#pragma unroll
            for (int q = 0; q < 4; ++q) acc[mi][nj][q] = 0.f;

    int ar = tid >> 2, ac = (tid & 3) * 8;
    int br = tid >> 4, bc = (tid & 15) * 8;
    const __half* Ap = A + (size_t)(bm + ar) * K + ac;
    const __half* Bp = B + (size_t)br * Ncols + bn + bc;

    int nstage = K >> 5;
    cp16(&As[0][ar][ac], Ap);
    cp16(&As[0][ar + 64][ac], Ap + (size_t)64 * K);
    cp16(&Bs[0][br][bc], Bp);
    cp16(&Bs[0][br + 16][bc], Bp + (size_t)16 * Ncols);
    cp_commit();
    if (nstage > 1) {
        cp16(&As[1][ar][ac], Ap + 32);
        cp16(&As[1][ar + 64][ac], Ap + (size_t)64 * K + 32);
        cp16(&Bs[1][br][bc], Bp + (size_t)32 * Ncols);
        cp16(&Bs[1][br + 16][bc], Bp + (size_t)48 * Ncols);
    }
    cp_commit();

    for (int s = 0; s < nstage; ++s) {
        int cur = s % 3;
        cp_wait1();
        __syncthreads();
        if (s + 2 < nstage) {
            int k0 = (s + 2) << 5;
            int nxt = (s + 2) % 3;
            cp16(&As[nxt][ar][ac], Ap + k0);
            cp16(&As[nxt][ar + 64][ac], Ap + (size_t)64 * K + k0);
            cp16(&Bs[nxt][br][bc], Bp + (size_t)k0 * Ncols);
            cp16(&Bs[nxt][br + 16][bc], Bp + (size_t)(k0 + 16) * Ncols);
        }
        cp_commit();
#pragma unroll
        for (int k16 = 0; k16 < 2; ++k16) {
            unsigned af[4][4], bf[4][2];
#pragma unroll
            for (int mi = 0; mi < 4; ++mi)
                ldsm4(af[mi][0], af[mi][1], af[mi][2], af[mi][3],
                      &As[cur][wm + mi * 16 + lr16][k16 * 16 + lh * 8]);
#pragma unroll
            for (int p = 0; p < 2; ++p) {
                unsigned r0, r1, r2, r3;
                ldsm4t(r0, r1, r2, r3, &Bs[cur][k16 * 16 + lr16][wn + p * 16 + lh * 8]);
                bf[2 * p][0] = r0; bf[2 * p][1] = r1;
                bf[2 * p + 1][0] = r2; bf[2 * p + 1][1] = r3;
            }
#pragma unroll
            for (int mi = 0; mi < 4; ++mi)
#pragma unroll
                for (int nj = 0; nj < 4; ++nj)
                    mma16816(acc[mi][nj], af[mi], bf[nj]);
        }
    }

    __syncthreads();
    int lr = lane >> 2, lc = lane & 3;
#pragma unroll
    for (int mi = 0; mi < 4; ++mi) {
#pragma unroll
        for (int nj = 0; nj < 4; ++nj) {
            int row = bm + wm + mi * 16 + lr;
            int col = bn + wn + nj * 8 + 2 * lc;
            float b0 = 0.f, b1 = 0.f;
            if (HASBIAS) { b0 = bias[col]; b1 = bias[col + 1]; }
            float v0 = acc[mi][nj][0] + b0, v1 = acc[mi][nj][1] + b1;
            float v2 = acc[mi][nj][2] + b0, v3 = acc[mi][nj][3] + b1;
            if (RELU) {
                v0 = fmaxf(v0, 0.f); v1 = fmaxf(v1, 0.f);
                v2 = fmaxf(v2, 0.f); v3 = fmaxf(v3, 0.f);
            }
            *(__half2*)(C + (size_t)row * Ncols + col) = __floats2half2_rn(v0, v1);
            *(__half2*)(C + (size_t)(row + 8) * Ncols + col) = __floats2half2_rn(v2, v3);
        }
    }
}

// ---------------- z_t = g_t @ Wfce + bfce ----------------
__global__ __launch_bounds__(256) void proj_z_kernel(const float* __restrict__ Wfce,
                                                     const float* __restrict__ bfce) {
    __shared__ float part[256];
    int t = blockIdx.x;
    int tid = threadIdx.x;
    int j = tid & 63;
    int kq = tid >> 6;
    float a = 0.f;
#pragma unroll 8
    for (int k = kq * 64; k < kq * 64 + 64; ++k)
        a += d_gpool[t * HH + k] * __ldg(&Wfce[k * LL + j]);
    part[tid] = a;
    __syncthreads();
    if (tid < 64)
        d_zs[t * LL + tid] = part[tid] + part[64 + tid] + part[128 + tid] + part[192 + tid]
                             + bfce[tid];
}

// ---------------- persistent 2-layer LSTM + head: smem-resident fp16 weights ----------------
__device__ __forceinline__ float sigm(float x) { return 1.f / (1.f + expf(-x)); }

__device__ __forceinline__ void cluster_bar() {
    asm volatile("barrier.cluster.arrive.aligned;" ::: "memory");
    asm volatile("barrier.cluster.wait.aligned;" ::: "memory");
}

#define LSTM_SMEM_H2 (256 * 64 + 64 * 64 + 256 * 64 + 256 * 64)
#define LSTM_SMEM_BYTES (LSTM_SMEM_H2 * 4)

__global__ __launch_bounds__(256) __cluster_dims__(LSTM_BLOCKS, 1, 1) void lstm_kernel(
    const __half2* __restrict__ Wih0, const __half2* __restrict__ Whh0,
    const float* __restrict__ bih0, const float* __restrict__ bhh0,
    const __half2* __restrict__ Wih1, const __half2* __restrict__ Whh1,
    const float* __restrict__ bih1, const float* __restrict__ bhh1,
    const float* __restrict__ Whead, const float* __restrict__ bhead)
{
    extern __shared__ __half2 wsm[];
    __half2* whh0_s = wsm;
    __half2* wih0_s = whh0_s + 256 * 64;
    __half2* whh1_s = wih0_s + 64 * 64;
    __half2* wih1_s = whh1_s + 256 * 64;
    __shared__ float x_sh[LL];
    __shared__ float h1_sh[HL];
    __shared__ float h2_sh[HL];
    __shared__ float2 part[256];
    int tid = threadIdx.x;
    int b = blockIdx.x;
    int p = tid & 63;
    int kq = tid >> 6;
    float c1 = 0.f, c2 = 0.f;
    if (tid < HL) { h1_sh[tid] = 0.f; h2_sh[tid] = 0.f; }

    for (int i = tid; i < 256 * 64; i += 256) {
        int k = i >> 6, pp = i & 63;
        whh0_s[i] = Whh0[(size_t)k * 512 + b * 64 + pp];
        whh1_s[i] = Whh1[(size_t)k * 512 + b * 64 + pp];
        wih1_s[i] = Wih1[(size_t)k * 512 + b * 64 + pp];
    }
    for (int i = tid; i < 64 * 64; i += 256) {
        int k = i >> 6, pp = i & 63;
        wih0_s[i] = Wih0[(size_t)k * 512 + b * 64 + pp];
    }
    __syncthreads();
    int round = 0;

    for (int t = 0; t < TT; ++t) {
        if (tid < LL) x_sh[tid] = d_zs[t * LL + tid];
        __syncthreads();

        float ax = 0.f, ay = 0.f;
#pragma unroll 8
        for (int k = kq * 64; k < kq * 64 + 64; ++k) {
            float h = h1_sh[k];
            float2 w = __half22float2(whh0_s[k * 64 + p]);
            ax += h * w.x; ay += h * w.y;
        }
#pragma unroll 8
        for (int k = kq * 16; k < kq * 16 + 16; ++k) {
            float x = x_sh[k];
            float2 w = __half22float2(wih0_s[k * 64 + p]);
            ax += x * w.x; ay += x * w.y;
        }
        part[tid] = make_float2(ax, ay);
        __syncthreads();
        int pb = round & 1;
        if (tid < 64) {
            float2 a0 = part[tid], a1 = part[64 + tid], a2 = part[128 + tid], a3 = part[192 + tid];
            float2 bi = ((const float2*)bih0)[b * 64 + tid];
            float2 bh = ((const float2*)bhh0)[b * 64 + tid];
            float2 g = make_float2(a0.x + a1.x + a2.x + a3.x + bi.x + bh.x,
                                   a0.y + a1.y + a2.y + a3.y + bi.y + bh.y);
            __stcg(&((float2*)&d_gates[pb][0])[b * 64 + tid], g);
        }
        round++;
        __threadfence();
        cluster_bar();
        {
            float gi = __ldcg(&d_gates[pb][tid]);
            float gf = __ldcg(&d_gates[pb][256 + tid]);
            float gg = __ldcg(&d_gates[pb][512 + tid]);
            float go = __ldcg(&d_gates[pb][768 + tid]);
            c1 = sigm(gf) * c1 + sigm(gi) * tanhf(gg);
            h1_sh[tid] = sigm(go) * tanhf(c1);
        }
        __syncthreads();

        ax = 0.f; ay = 0.f;
#pragma unroll 8
        for (int k = kq * 64; k < kq * 64 + 64; ++k) {
            float h2v = h2_sh[k];
            float h1v = h1_sh[k];
            float2 wh = __half22float2(whh1_s[k * 64 + p]);
            float2 wi = __half22float2(wih1_s[k * 64 + p]);
            ax += h2v * wh.x + h1v * wi.x;
            ay += h2v * wh.y + h1v * wi.y;
        }
        part[tid] = make_float2(ax, ay);
        __syncthreads();
        pb = round & 1;
        if (tid < 64) {
            float2 a0 = part[tid], a1 = part[64 + tid], a2 = part[128 + tid], a3 = part[192 + tid];
            float2 bi = ((const float2*)bih1)[b * 64 + tid];
            float2 bh = ((const float2*)bhh1)[b * 64 + tid];
            float2 g = make_float2(a0.x + a1.x + a2.x + a3.x + bi.x + bh.x,
                                   a0.y + a1.y + a2.y + a3.y + bi.y + bh.y);
            __stcg(&((float2*)&d_gates[pb][0])[b * 64 + tid], g);
        }
        round++;
        __threadfence();
        cluster_bar();
        {
            float gi = __ldcg(&d_gates[pb][tid]);
            float gf = __ldcg(&d_gates[pb][256 + tid]);
            float gg = __ldcg(&d_gates[pb][512 + tid]);
            float go = __ldcg(&d_gates[pb][768 + tid]);
            c2 = sigm(gf) * c2 + sigm(gi) * tanhf(gg);
            h2_sh[tid] = sigm(go) * tanhf(c2);
        }
        __syncthreads();
    }

    if (b == 0 && tid < LL) {
        float a = bhead[tid];
        for (int k = 0; k < HL; ++k)
            a += h2_sh[k] * Whead[k * LL + tid];
        d_zfin[tid] = a;
    }
}

// ---------------- decoder fc: relu(z @ Wfcd + bfcd) -> half [N, L] ----------------
__global__ void fcd_kernel(const float* __restrict__ Wfcd, const float* __restrict__ bfcd,
                           __half2* __restrict__ out) {
    __shared__ float z[LL];
    if (threadIdx.x < LL) z[threadIdx.x] = d_zfin[threadIdx.x];
    __syncthreads();
    int q = blockIdx.x * blockDim.x + threadIdx.x;
    if (q >= NN * LL / 2) return;
    float2 bb = ((const float2*)bfcd)[q];
    float ax = bb.x, ay = bb.y;
#pragma unroll 8
    for (int k = 0; k < LL; ++k) {
        float2 w = ((const float2*)(Wfcd + (size_t)k * (NN * LL)))[q];
        ax += z[k] * w.x;
        ay += z[k] * w.y;
    }
    out[q] = __floats2half2_rn(fmaxf(ax, 0.f), fmaxf(ay, 0.f));
}

// ---------------- launch ----------------
extern "C" void kernel_launch(void* const* d_in, const int* in_sizes, int n_in,
                              void* d_out, int out_size) {
    const float* xs        = (const float*)d_in[0];
    const float* edge_attr = (const float*)d_in[1];
    const float* We0  = (const float*)d_in[2];
    const float* be0  = (const float*)d_in[3];
    const float* We1  = (const float*)d_in[4];
    const float* be1  = (const float*)d_in[5];
    const float* Wfce = (const float*)d_in[6];
    const float* bfce = (const float*)d_in[7];
    const float* Wih0 = (const float*)d_in[8];
    const float* Whh0 = (const float*)d_in[9];
    const float* bih0 = (const float*)d_in[10];
    const float* bhh0 = (const float*)d_in[11];
    const float* Wih1 = (const float*)d_in[12];
    const float* Whh1 = (const float*)d_in[13];
    const float* bih1 = (const float*)d_in[14];
    const float* bhh1 = (const float*)d_in[15];
    const float* Whead = (const float*)d_in[16];
    const float* bhead = (const float*)d_in[17];
    const float* Wfcd = (const float*)d_in[18];
    const float* bfcd = (const float*)d_in[19];
    const float* Wd0  = (const float*)d_in[20];
    const float* bd0  = (const float*)d_in[21];
    const float* Wd1  = (const float*)d_in[22];
    const float* bd1  = (const float*)d_in[23];
    const float* Wd2  = (const float*)d_in[24];
    const float* bd2  = (const float*)d_in[25];
    const void*  eidx = d_in[26];

    float *buf0, *buf1, *degE, *degD, *gpool;
    int *cnt;
    __half *hbuf, *we0h, *we1h, *wd0h, *wd1h, *wd2h, *wih0h, *whh0h, *wih1h, *whh1h;
    unsigned char *x8, *h8;
    cudaGetSymbolAddress((void**)&buf0, d_buf0);
    cudaGetSymbolAddress((void**)&buf1, d_buf1);
    cudaGetSymbolAddress((void**)&hbuf, d_hbuf);
    cudaGetSymbolAddress((void**)&x8, d_x8);
    cudaGetSymbolAddress((void**)&h8, d_h8);
    cudaGetSymbolAddress((void**)&we0h, d_We0h);
    cudaGetSymbolAddress((void**)&we1h, d_We1h);
    cudaGetSymbolAddress((void**)&wd0h, d_Wd0h);
    cudaGetSymbolAddress((void**)&wd1h, d_Wd1h);
    cudaGetSymbolAddress((void**)&wd2h, d_Wd2h);
    cudaGetSymbolAddress((void**)&wih0h, d_Wih0h);
    cudaGetSymbolAddress((void**)&whh0h, d_Whh0h);
    cudaGetSymbolAddress((void**)&wih1h, d_Wih1h);
    cudaGetSymbolAddress((void**)&whh1h, d_Whh1h);
    cudaGetSymbolAddress((void**)&degE, d_deg_enc);
    cudaGetSymbolAddress((void**)&degD, d_deg_dec);
    cudaGetSymbolAddress((void**)&gpool, d_gpool);
    cudaGetSymbolAddress((void**)&cnt, d_cnt);

    const int MPAD = 10112;

    static cudaStream_t s2 = [](){ cudaStream_t t; cudaStreamCreateWithFlags(&t, cudaStreamNonBlocking); return t; }();
    static cudaEvent_t evFork = [](){ cudaEvent_t e; cudaEventCreateWithFlags(&e, cudaEventDisableTiming); return e; }();
    static cudaEvent_t evJoin = [](){ cudaEvent_t e; cudaEventCreateWithFlags(&e, cudaEventDisableTiming); return e; }();
    static cudaEvent_t evMid  = [](){ cudaEvent_t e; cudaEventCreateWithFlags(&e, cudaEventDisableTiming); return e; }();
    static cudaEvent_t evJoin2 = [](){ cudaEvent_t e; cudaEventCreateWithFlags(&e, cudaEventDisableTiming); return e; }();
    static bool attrSet = [](){
        cudaFuncSetAttribute(lstm_kernel, cudaFuncAttributeMaxDynamicSharedMemorySize, LSTM_SMEM_BYTES);
        cudaFuncSetAttribute(hgemm_fused<128, true>, cudaFuncAttributeMaxDynamicSharedMemorySize, FUSED_SMEM_BYTES);
        cudaFuncSetAttribute(hgemm_fused<64, false>, cudaFuncAttributeMaxDynamicSharedMemorySize, FUSED_SMEM_BYTES);
        return true;
    }();
    (void)attrSet;

    cudaEventRecord(evFork, 0);
    cudaStreamWaitEvent(s2, evFork, 0);
    f2h_all_kernel<<<(N2_TOT + 255) / 256, 256, 0, s2>>>(
        xs, We0, We1, Wd0, Wd1, Wd2, Wih0, Whh0, Wih1, Whh1,
        (unsigned short*)x8, (__half2*)we0h, (__half2*)we1h,
        (__half2*)wd0h, (__half2*)wd1h, (__half2*)wd2h,
        (__half2*)wih0h, (__half2*)whh0h, (__half2*)wih1h, (__half2*)whh1h);
    cudaEventRecord(evJoin, s2);

    // ---- preprocessing (main stream): memset nodes + detect + count/scan/fill ----
    cudaMemsetAsync(degE, 0, NN * sizeof(float), 0);
    cudaMemsetAsync(degD, 0, NN * sizeof(float), 0);
    cudaMemsetAsync(cnt, 0, NN * sizeof(int), 0);
    cudaMemsetAsync(gpool, 0, TT * HH * sizeof(float), 0);
    detect_kernel<<<1, 32>>>(eidx);
    count_kernel<<<(EN + 255) / 256, 256>>>(eidx, edge_attr);
    scanA_kernel<<<10, 1024>>>();
    scanC_kernel<<<10, 1024>>>();
    fill_kernel<<<(EN + 255) / 256, 256>>>(eidx, edge_attr);

    cudaStreamWaitEvent(0, evJoin, 0);

    // ---- encoder (fp8 gathers, fused double GEMM) ----
    agg_enc0_kernel<<<NN, 128>>>((const uint4*)x8, (uint4*)buf0);
    hgemm_fused<128, true><<<TT * NN / 128, 256, FUSED_SMEM_BYTES>>>(
        (const __half*)buf0, we0h, be0, we1h, h8, TT * NN);
    agg_pool_kernel<<<1250, 256>>>((const uint4*)h8, be1);
    proj_z_kernel<<<TT, 256>>>(Wfce, bfce);

    // fork: warm first 96MB of Wfcd into L2 while the LSTM runs on 8 SMs
    cudaEventRecord(evMid, 0);
    cudaStreamWaitEvent(s2, evMid, 0);
    prefetch_kernel<<<1024, 256, 0, s2>>>((const float4*)Wfcd, 6291456);
    cudaEventRecord(evJoin2, s2);

    // ---- LSTM + head (smem-resident weights) ----
    lstm_kernel<<<LSTM_BLOCKS, 256, LSTM_SMEM_BYTES>>>(
        (const __half2*)wih0h, (const __half2*)whh0h, bih0, bhh0,
        (const __half2*)wih1h, (const __half2*)whh1h, bih1, bhh1, Whead, bhead);

    cudaStreamWaitEvent(0, evJoin2, 0);

    // ---- decoder (fp16, fused first GEMM pair) ----
    fcd_kernel<<<(NN * LL / 2 + 255) / 256, 256>>>(Wfcd, bfcd, (__half2*)hbuf);
    agg_dec_kernel<LL / 2, 4, false, false><<<(NN + 3) / 4, 128>>>(
        (const __half2*)hbuf, (__half*)buf0, nullptr);
    hgemm_fused<64, false><<<MPAD / 128, 256, FUSED_SMEM_BYTES>>>(
        (const __half*)buf0, wd0h, bd0, wd1h, hbuf, MPAD);
    agg_dec_kernel<HH / 2, 2, true, false><<<(NN + 1) / 2, 256>>>(
        (const __half2*)hbuf, (__half*)buf0, bd1);
    hgemm<false, false><<<dim3(MPAD / 128, FF / 128), 256>>>(
        (const __half*)buf0, wd2h, nullptr, (__half*)buf1, MPAD, HH, FF);
    agg_dec_kernel<FF / 2, 2, false, true><<<(NN + 1) / 2, 128>>>(
        (const __half2*)buf1, (float*)d_out, bd2);
}